// round 10
// baseline (speedup 1.0000x reference)
#include <cuda_runtime.h>
#include <cuda_bf16.h>
#include <cstdint>

// Problem shapes (fixed for this dataset entry)
constexpr int B = 4;
constexpr int S = 4096;
constexpr int D = 2048;
constexpr int HALO  = 8;        // recurrence depth N_BLANKS
constexpr int NROWS = 2048;     // x values span [0, 2048)
constexpr int NTOK  = B * S;    // 16384 tokens
constexpr int TTW   = 64;       // weights-kernel t-tile

// Device scratch (no allocs allowed)
__device__ float    g_w[NTOK * HALO];     // w_1..w_8 per token
__device__ unsigned g_flag[NTOK];         // nonzero-weight mask per token
__device__ int      g_cnt[NROWS];         // row histogram
__device__ int      g_off[NROWS + 1];     // row start offsets
__device__ int      g_cur[NROWS];         // scatter cursors
__device__ int      g_order[NTOK];        // token ids grouped by row
__device__ int      g_slow[NTOK];         // slow-path token list
__device__ int      g_nslow;              // slow-path count

// ---------------------------------------------------------------------------
// K0: zero counters
// ---------------------------------------------------------------------------
__global__ void zero_kernel()
{
    const int i = blockIdx.x * blockDim.x + threadIdx.x;
    if (i < NROWS) g_cnt[i] = 0;
    if (i == 0)    g_nslow = 0;
}

// ---------------------------------------------------------------------------
// K1: weight DP per t-tile (+ row histogram + slow-token list)
//   w^k[t][j] = w^{k-1}[t][j] + p[t-k] * w^{k-1}[t-1][j-1],  w_0 == 1 implicit
//   p[t] = (x[t] >= 16) && (x[t+1] < 16), zero outside [0, S-1)
// ---------------------------------------------------------------------------
__global__ __launch_bounds__(128)
void weights_kernel(const int* __restrict__ x)
{
    const int b   = blockIdx.y;
    const int T0  = blockIdx.x * TTW;
    const int tid = threadIdx.x;

    // row histogram (independent of DP)
    if (tid < TTW) atomicAdd(&g_cnt[x[b * S + T0 + tid]], 1);

    __shared__ float sp[TTW + 2 * HALO];             // p[t], t = T0-2*HALO+i
    __shared__ float wbuf[2][TTW + HALO][HALO];

    for (int i = tid; i < TTW + 2 * HALO; i += 128) {
        int t = T0 - 2 * HALO + i;
        float pv = 0.0f;
        if (t >= 0 && t + 1 < S) {
            int xt  = x[b * S + t];
            int xt1 = x[b * S + t + 1];
            pv = (xt1 < 16 && xt >= 16) ? 1.0f : 0.0f;
        }
        sp[i] = pv;
    }
    float wloc[HALO];
#pragma unroll
    for (int j = 0; j < HALO; j++) wloc[j] = 0.0f;
    if (tid < TTW + HALO) {
#pragma unroll
        for (int j = 0; j < HALO; j++) wbuf[0][tid][j] = 0.0f;
    }
    __syncthreads();

    for (int k = 1; k <= HALO; k++) {
        const int cur = k & 1, prv = cur ^ 1;
        if (tid < TTW + HALO) {
            float nb[HALO - 1];
            float nb0 = 0.0f;
            if (tid > 0) {
                nb0 = 1.0f;
#pragma unroll
                for (int j = 0; j < HALO - 1; j++) nb[j] = wbuf[prv][tid - 1][j];
            } else {
#pragma unroll
                for (int j = 0; j < HALO - 1; j++) nb[j] = 0.0f;
            }
            const float pv = sp[tid + HALO - k];
            wloc[0] = fmaf(pv, nb0, wloc[0]);
#pragma unroll
            for (int j = 1; j < HALO; j++) wloc[j] = fmaf(pv, nb[j - 1], wloc[j]);
#pragma unroll
            for (int j = 0; j < HALO; j++) wbuf[cur][tid][j] = wloc[j];
        }
        __syncthreads();
    }

    if (tid >= HALO && tid < TTW + HALO) {
        const int t  = T0 - HALO + tid;              // in [T0, T0+TTW)
        const int tf = b * S + t;
        unsigned m = 0;
#pragma unroll
        for (int j = 0; j < HALO; j++) {
            if (wloc[j] != 0.0f) m |= (1u << (j + 1));
            g_w[(size_t)tf * HALO + j] = wloc[j];
        }
        g_flag[tf] = m;
        if (m) {
            const int pos = atomicAdd(&g_nslow, 1);
            g_slow[pos] = tf;
        }
    }
}

// ---------------------------------------------------------------------------
// K2: exclusive prefix over g_cnt -> g_off, g_cur  (one block, 1024 threads)
// ---------------------------------------------------------------------------
__global__ __launch_bounds__(1024)
void prefix_kernel()
{
    __shared__ int sa[NROWS], sb[NROWS];
    const int tid = threadIdx.x;

    sa[tid]        = g_cnt[tid];
    sa[tid + 1024] = g_cnt[tid + 1024];
    __syncthreads();

    int* src = sa;
    int* dst = sb;
    for (int off = 1; off < NROWS; off <<= 1) {
#pragma unroll
        for (int e = 0; e < 2; e++) {
            const int i = tid + e * 1024;
            dst[i] = src[i] + (i >= off ? src[i - off] : 0);
        }
        __syncthreads();
        int* tmp = src; src = dst; dst = tmp;
    }
    // src = inclusive scan
#pragma unroll
    for (int e = 0; e < 2; e++) {
        const int i = tid + e * 1024;
        g_off[i + 1] = src[i];
        const int ex = (i == 0) ? 0 : src[i - 1];
        g_cur[i] = ex;
        if (i == 0) g_off[0] = 0;
    }
}

// ---------------------------------------------------------------------------
// K3: scatter token ids into row-grouped order
// ---------------------------------------------------------------------------
__global__ __launch_bounds__(1024)
void scatter_kernel(const int* __restrict__ x)
{
    const int i = blockIdx.x * blockDim.x + threadIdx.x;
    if (i < NTOK) {
        const int pos = atomicAdd(&g_cur[x[i]], 1);
        g_order[pos] = i;
    }
}

// ---------------------------------------------------------------------------
// K4: fast path. One block per row: load 8KB row once (1 float4/thread),
//     stream it to every fast-path (flag==0) destination.
// ---------------------------------------------------------------------------
__global__ __launch_bounds__(512)
void fast_kernel(const float* __restrict__ emb, float* __restrict__ out)
{
    const int r   = blockIdx.x;
    const int tid = threadIdx.x;
    const int lo  = g_off[r];
    const int hi  = g_off[r + 1];
    if (lo == hi) return;

    __shared__ int      socc[64];
    __shared__ unsigned sfl[64];

    const float4 e = *reinterpret_cast<const float4*>(emb + (size_t)r * D + tid * 4);

    for (int base = lo; base < hi; base += 64) {
        const int n = min(64, hi - base);
        if (tid < n) {
            const int idx = g_order[base + tid];
            socc[tid] = idx;
            sfl[tid]  = g_flag[idx];
        }
        __syncthreads();
        for (int k = 0; k < n; k++) {
            if (sfl[k] == 0) {
                __stcs(reinterpret_cast<float4*>(out + (size_t)socc[k] * D + tid * 4), e);
            }
        }
        __syncthreads();
    }
}

// ---------------------------------------------------------------------------
// K5: slow path. Grid-stride over slow tokens; full formula per token.
//     out[t] = e[x[t]] + sum_j w_j(t) * e[x[t-j]]
// ---------------------------------------------------------------------------
__global__ __launch_bounds__(512)
void slow_kernel(const int* __restrict__ x,
                 const float* __restrict__ emb,
                 float* __restrict__ out)
{
    const int tid = threadIdx.x;
    const int n   = g_nslow;

    for (int it = blockIdx.x; it < n; it += gridDim.x) {
        const int tf = g_slow[it];
        const int t  = tf & (S - 1);
        const unsigned m = g_flag[tf];

        float4 c = *reinterpret_cast<const float4*>(
            emb + (size_t)x[tf] * D + tid * 4);
#pragma unroll
        for (int j = 1; j <= HALO; j++) {
            if ((m >> j) & 1u) {
                // m bit j set implies w_j != 0 implies t - j >= 0 (boundary p's are 0)
                const float  w = g_w[(size_t)tf * HALO + (j - 1)];
                const float4 h = *reinterpret_cast<const float4*>(
                    emb + (size_t)x[tf - j] * D + tid * 4);
                c.x = fmaf(h.x, w, c.x);
                c.y = fmaf(h.y, w, c.y);
                c.z = fmaf(h.z, w, c.z);
                c.w = fmaf(h.w, w, c.w);
            }
        }
        __stcs(reinterpret_cast<float4*>(out + (size_t)tf * D + tid * 4), c);
    }
}

extern "C" void kernel_launch(void* const* d_in, const int* in_sizes, int n_in,
                              void* d_out, int out_size)
{
    const int*   x   = (const int*)d_in[0];
    const float* emb = (const float*)d_in[1];
    float*       out = (float*)d_out;

    zero_kernel<<<(NROWS + 1023) / 1024, 1024>>>();
    dim3 gridW(S / TTW, B);                 // 64 x 4
    weights_kernel<<<gridW, 128>>>(x);
    prefix_kernel<<<1, 1024>>>();
    scatter_kernel<<<(NTOK + 1023) / 1024, 1024>>>(x);
    fast_kernel<<<NROWS, 512>>>(emb, out);  // one block per row
    slow_kernel<<<1024, 512>>>(x, emb, out);
}